// round 4
// baseline (speedup 1.0000x reference)
#include <cuda_runtime.h>

#define BB 64
#define CC 512
#define HH 28
#define WW 28
#define HWSZ (HH*WW)
#define HID 32
#define NPLANE (BB*CC)
#define NLAYERS 4
#define QPP 196            // float4 quads per plane

// Scratch (static device memory -- allocation-free)
__device__ float g_buf[(size_t)NPLANE * HWSZ];   // ping-pong x buffer (~103MB)
__device__ float g_seq[NPLANE];                  // pooled means [B,C]
__device__ float g_ht[NPLANE];                   // LSTM hidden
__device__ float g_ct[NPLANE];                   // LSTM cell
__device__ float g_gi[BB * 3 * CC];              // input-path gates (reused by 2nd cell)
__device__ float g_gh2[3 * CC];                  // 2nd cell hidden-path gates (row 0)
__device__ float g_scale[NPLANE];                // per-plane scale = 1 + sigm(ncx2)

__device__ __forceinline__ float sigmf(float x) { return 1.0f / (1.0f + __expf(-x)); }

// Reduce two sums simultaneously across the block.
__device__ __forceinline__ void blockReduceSum2(float& a, float& b) {
    __shared__ float redA[32], redB[32];
    int lane = threadIdx.x & 31, w = threadIdx.x >> 5;
    #pragma unroll
    for (int o = 16; o; o >>= 1) {
        a += __shfl_down_sync(0xffffffffu, a, o);
        b += __shfl_down_sync(0xffffffffu, b, o);
    }
    if (lane == 0) { redA[w] = a; redB[w] = b; }
    __syncthreads();
    int nw = (blockDim.x + 31) >> 5;
    a = (threadIdx.x < nw) ? redA[threadIdx.x] : 0.f;
    b = (threadIdx.x < nw) ? redB[threadIdx.x] : 0.f;
    if (w == 0) {
        #pragma unroll
        for (int o = 16; o; o >>= 1) {
            a += __shfl_down_sync(0xffffffffu, a, o);
            b += __shfl_down_sync(0xffffffffu, b, o);
        }
    }
}

// Initial pool of x + zero LSTM state. Two contiguous planes per block.
__global__ void __launch_bounds__(256) k_pool_init(const float* __restrict__ x) {
    int p0 = blockIdx.x * 2, tid = threadIdx.x;
    const float4* in4 = (const float4*)(x + (size_t)p0 * HWSZ);
    float s0 = 0.f, s1 = 0.f;
    #pragma unroll
    for (int i = tid; i < 2 * QPP; i += 256) {
        float4 v = in4[i];
        float t = v.x + v.y + v.z + v.w;
        if (i < QPP) s0 += t; else s1 += t;
    }
    blockReduceSum2(s0, s1);
    if (tid == 0) {
        g_seq[p0] = s0 * (1.0f / HWSZ);
        g_seq[p0 + 1] = s1 * (1.0f / HWSZ);
    }
    if (tid < 2) {
        g_ht[p0 + tid] = 0.f;
        g_ct[p0 + tid] = 0.f;
    }
}

// Fused cell: bottleneck GEMVs (both paths) + gate update for one batch b per block.
// Block 0 additionally computes the second cell's hidden path (ht[0] -> g_gh2).
__global__ void __launch_bounds__(512) k_cell(
        const float* __restrict__ w_ih_l1, const float* __restrict__ b_ih_l1,
        const float* __restrict__ w_ih_l2, const float* __restrict__ b_ih_l2,
        const float* __restrict__ w_hh_l1, const float* __restrict__ b_hh_l1,
        const float* __restrict__ w_hh_l2, const float* __restrict__ b_hh_l2) {
    __shared__ __align__(16) float sin0[CC], sin1[CC];
    __shared__ float hi[HID], hh[HID];
    int b = blockIdx.x, tid = threadIdx.x, lane = tid & 31, w = tid >> 5;  // 16 warps

    if (tid < 128)      ((float4*)sin0)[tid]       = ((const float4*)(g_seq + b * CC))[tid];
    else if (tid < 256) ((float4*)sin1)[tid - 128] = ((const float4*)(g_ht + b * CC))[tid - 128];
    __syncthreads();

    // Phase 1: 64 dots of length 512 (2 paths x 32 hidden), float4 loads.
    #pragma unroll
    for (int t = 0; t < 4; t++) {
        int d = w + 16 * t;
        int path = d >> 5, k = d & 31;
        const float4* wr4 = (const float4*)((path ? w_hh_l1 : w_ih_l1) + k * CC);
        const float4* in4 = (const float4*)(path ? sin1 : sin0);
        float s = 0.f;
        #pragma unroll
        for (int j = lane; j < 128; j += 32) {
            float4 wv = wr4[j], iv = in4[j];
            s += iv.x * wv.x + iv.y * wv.y + iv.z * wv.z + iv.w * wv.w;
        }
        #pragma unroll
        for (int o = 16; o; o >>= 1) s += __shfl_down_sync(0xffffffffu, s, o);
        if (lane == 0) {
            float v = fmaxf(s + (path ? b_hh_l1 : b_ih_l1)[k], 0.f);
            if (path) hh[k] = v; else hi[k] = v;
        }
    }
    __syncthreads();

    // Phase 2: per-channel gate update (c = tid), float4 weight loads.
    int c = tid;
    float gi[3], gh[3];
    #pragma unroll
    for (int g = 0; g < 3; g++) { gi[g] = b_ih_l2[g * CC + c]; gh[g] = b_hh_l2[g * CC + c]; }
    #pragma unroll
    for (int g = 0; g < 3; g++) {
        const float4* wi4 = (const float4*)&w_ih_l2[(g * CC + c) * HID];
        const float4* wh4 = (const float4*)&w_hh_l2[(g * CC + c) * HID];
        #pragma unroll
        for (int q = 0; q < 8; q++) {
            float4 wi = wi4[q], wh = wh4[q];
            int k = q * 4;
            gi[g] += hi[k] * wi.x + hi[k+1] * wi.y + hi[k+2] * wi.z + hi[k+3] * wi.w;
            gh[g] += hh[k] * wh.x + hh[k+1] * wh.y + hh[k+2] * wh.z + hh[k+3] * wh.w;
        }
    }
    #pragma unroll
    for (int g = 0; g < 3; g++) g_gi[(b * 3 + g) * CC + c] = gi[g];
    float ig = sigmf(gi[0] + gh[0]);
    float fg = sigmf(gi[1] + gh[1]);
    float cg = tanhf(gi[2] + gh[2]);
    float nc = fg * g_ct[b * CC + c] + ig * cg;
    float nh = sigmf(nc);
    g_ct[b * CC + c] = nc;
    g_ht[b * CC + c] = nh;

    // Block-0 tail: second cell's hidden path with hx = ht[0] (our own fresh nh).
    if (b == 0) {
        sin0[c] = nh;
        __syncthreads();
        #pragma unroll
        for (int t = 0; t < 2; t++) {
            int k = w + 16 * t;
            const float4* wr4 = (const float4*)(w_hh_l1 + k * CC);
            const float4* in4 = (const float4*)sin0;
            float s = 0.f;
            #pragma unroll
            for (int j = lane; j < 128; j += 32) {
                float4 wv = wr4[j], iv = in4[j];
                s += iv.x * wv.x + iv.y * wv.y + iv.z * wv.z + iv.w * wv.w;
            }
            #pragma unroll
            for (int o = 16; o; o >>= 1) s += __shfl_down_sync(0xffffffffu, s, o);
            if (lane == 0) hi[k] = fmaxf(s + b_hh_l1[k], 0.f);
        }
        __syncthreads();
        #pragma unroll
        for (int j = tid; j < 3 * CC; j += 512) {
            float acc = b_hh_l2[j];
            const float4* wh4 = (const float4*)&w_hh_l2[j * HID];
            #pragma unroll
            for (int q = 0; q < 8; q++) {
                float4 wh = wh4[q];
                int k = q * 4;
                acc += hi[k] * wh.x + hi[k+1] * wh.y + hi[k+2] * wh.z + hi[k+3] * wh.w;
            }
            g_gh2[j] = acc;
        }
    }
}

// Per-plane scale = 1 + sigm(second-cell ncx). One thread per (b,c).
__global__ void __launch_bounds__(256) k_scale() {
    int idx = blockIdx.x * 256 + threadIdx.x;
    int b = idx >> 9, c = idx & 511;
    float i2 = g_gi[(b * 3 + 0) * CC + c] + g_gh2[c];
    float f2 = g_gi[(b * 3 + 1) * CC + c] + g_gh2[CC + c];
    float c2 = g_gi[(b * 3 + 2) * CC + c] + g_gh2[2 * CC + c];
    float nc2 = sigmf(f2) * g_ct[c] + sigmf(i2) * tanhf(c2);
    g_scale[idx] = 1.0f + sigmf(nc2);
}

// Fused update: x_new = x*scale + dwconv3x3(x); plane means for next layer.
// Two contiguous planes per block, 256 threads.
__global__ void __launch_bounds__(256) k_update(
        const float* __restrict__ xin, float* __restrict__ xout,
        const float* __restrict__ dw, int writeSeq) {
    int p0 = blockIdx.x * 2, tid = threadIdx.x;
    __shared__ __align__(16) float s[2 * HWSZ];
    __shared__ float sSc[2];

    const float4* in4 = (const float4*)(xin + (size_t)p0 * HWSZ);
    #pragma unroll
    for (int i = tid; i < 2 * QPP; i += 256) ((float4*)s)[i] = in4[i];
    if (tid < 2) sSc[tid] = g_scale[p0 + tid];
    __syncthreads();

    float4* out4 = (float4*)(xout + (size_t)p0 * HWSZ);
    float sum0 = 0.f, sum1 = 0.f;
    #pragma unroll
    for (int i = tid; i < 2 * QPP; i += 256) {
        int pl = (i >= QPP);
        int q = i - pl * QPP;                  // quad within plane
        const float* sp = s + pl * HWSZ;
        int c = (p0 + pl) & 511;
        const float* wq = dw + c * 9;
        float scale = sSc[pl];
        float o[4];
        float lsum = 0.f;
        #pragma unroll
        for (int u = 0; u < 4; u++) {
            int p = q * 4 + u;
            int y = p / WW, x = p - y * WW;
            float conv = 0.f;
            #pragma unroll
            for (int dy = -1; dy <= 1; dy++) {
                int yy = y + dy;
                if (yy < 0 || yy >= HH) continue;
                #pragma unroll
                for (int dx = -1; dx <= 1; dx++) {
                    int xx = x + dx;
                    if (xx < 0 || xx >= WW) continue;
                    conv += wq[(dy + 1) * 3 + (dx + 1)] * sp[yy * WW + xx];
                }
            }
            o[u] = sp[p] * scale + conv;
            lsum += o[u];
        }
        out4[i] = make_float4(o[0], o[1], o[2], o[3]);
        if (pl) sum1 += lsum; else sum0 += lsum;
    }
    if (writeSeq) {
        __syncthreads();   // reuse of red[] arrays inside reduce is safe after this
        blockReduceSum2(sum0, sum1);
        if (tid == 0) {
            g_seq[p0] = sum0 * (1.0f / HWSZ);
            g_seq[p0 + 1] = sum1 * (1.0f / HWSZ);
        }
    }
}

extern "C" void kernel_launch(void* const* d_in, const int* in_sizes, int n_in,
                              void* d_out, int out_size) {
    const float* x        = (const float*)d_in[0];
    const float* w_ih_l1  = (const float*)d_in[1];
    const float* b_ih_l1  = (const float*)d_in[2];
    const float* w_ih_l2  = (const float*)d_in[3];
    const float* b_ih_l2  = (const float*)d_in[4];
    const float* w_hh_l1  = (const float*)d_in[5];
    const float* b_hh_l1  = (const float*)d_in[6];
    const float* w_hh_l2  = (const float*)d_in[7];
    const float* b_hh_l2  = (const float*)d_in[8];
    const float* dw       = (const float*)d_in[9];
    float* out = (float*)d_out;

    float* buf = nullptr;
    cudaGetSymbolAddress((void**)&buf, g_buf);

    k_pool_init<<<NPLANE / 2, 256>>>(x);

    const float* cur = x;
    for (int l = 0; l < NLAYERS; l++) {
        k_cell<<<BB, 512>>>(w_ih_l1, b_ih_l1, w_ih_l2, b_ih_l2,
                            w_hh_l1, b_hh_l1, w_hh_l2, b_hh_l2);
        k_scale<<<NPLANE / 256, 256>>>();
        float* nxt = ((l & 1) == 0) ? buf : out;   // l0->buf, l1->out, l2->buf, l3->out
        k_update<<<NPLANE / 2, 256>>>(cur, nxt, dw, (l < NLAYERS - 1) ? 1 : 0);
        cur = nxt;
    }
}

// round 5
// speedup vs baseline: 1.2961x; 1.2961x over previous
#include <cuda_runtime.h>

#define BB 64
#define CC 512
#define HH 28
#define WW 28
#define HWSZ (HH*WW)
#define HID 32
#define NPLANE (BB*CC)
#define NLAYERS 4
#define QPP 196            // float4 quads per plane

// Scratch (static device memory -- allocation-free)
__device__ float g_buf[(size_t)NPLANE * HWSZ];   // ping-pong x buffer (~103MB)
__device__ float g_seq[NPLANE];                  // pooled means [B,C]
__device__ float g_ht[NPLANE];                   // LSTM hidden
__device__ float g_ct[NPLANE];                   // LSTM cell
__device__ float g_gi[BB * 3 * CC];              // input-path gates (reused by 2nd cell)
__device__ float g_gh2[3 * CC];                  // 2nd cell hidden-path gates (row 0)
__device__ float g_scale[NPLANE];                // per-plane scale = 1 + sigm(ncx2)

__device__ __forceinline__ float sigmf(float x) { return 1.0f / (1.0f + __expf(-x)); }

// Reduce two sums simultaneously across the block.
__device__ __forceinline__ void blockReduceSum2(float& a, float& b) {
    __shared__ float redA[32], redB[32];
    int lane = threadIdx.x & 31, w = threadIdx.x >> 5;
    #pragma unroll
    for (int o = 16; o; o >>= 1) {
        a += __shfl_down_sync(0xffffffffu, a, o);
        b += __shfl_down_sync(0xffffffffu, b, o);
    }
    if (lane == 0) { redA[w] = a; redB[w] = b; }
    __syncthreads();
    int nw = (blockDim.x + 31) >> 5;
    a = (threadIdx.x < nw) ? redA[threadIdx.x] : 0.f;
    b = (threadIdx.x < nw) ? redB[threadIdx.x] : 0.f;
    if (w == 0) {
        #pragma unroll
        for (int o = 16; o; o >>= 1) {
            a += __shfl_down_sync(0xffffffffu, a, o);
            b += __shfl_down_sync(0xffffffffu, b, o);
        }
    }
}

// Initial pool of x + zero LSTM state. Two contiguous planes per block.
__global__ void __launch_bounds__(256) k_pool_init(const float* __restrict__ x) {
    int p0 = blockIdx.x * 2, tid = threadIdx.x;
    const float4* in4 = (const float4*)(x + (size_t)p0 * HWSZ);
    float s0 = 0.f, s1 = 0.f;
    #pragma unroll
    for (int i = tid; i < 2 * QPP; i += 256) {
        float4 v = in4[i];
        float t = v.x + v.y + v.z + v.w;
        if (i < QPP) s0 += t; else s1 += t;
    }
    blockReduceSum2(s0, s1);
    if (tid == 0) {
        g_seq[p0] = s0 * (1.0f / HWSZ);
        g_seq[p0 + 1] = s1 * (1.0f / HWSZ);
    }
    if (tid < 2) {
        g_ht[p0 + tid] = 0.f;
        g_ct[p0 + tid] = 0.f;
    }
}

// Fused cell: bottleneck GEMVs (both paths) + gate update for one batch b per block.
// Block 0 additionally computes the second cell's hidden path (ht[0] -> g_gh2).
__global__ void __launch_bounds__(512) k_cell(
        const float* __restrict__ w_ih_l1, const float* __restrict__ b_ih_l1,
        const float* __restrict__ w_ih_l2, const float* __restrict__ b_ih_l2,
        const float* __restrict__ w_hh_l1, const float* __restrict__ b_hh_l1,
        const float* __restrict__ w_hh_l2, const float* __restrict__ b_hh_l2) {
    __shared__ __align__(16) float sin0[CC], sin1[CC];
    __shared__ float hi[HID], hh[HID];
    int b = blockIdx.x, tid = threadIdx.x, lane = tid & 31, w = tid >> 5;  // 16 warps

    if (tid < 128)      ((float4*)sin0)[tid]       = ((const float4*)(g_seq + b * CC))[tid];
    else if (tid < 256) ((float4*)sin1)[tid - 128] = ((const float4*)(g_ht + b * CC))[tid - 128];
    __syncthreads();

    // Phase 1: 64 dots of length 512 (2 paths x 32 hidden), float4 loads.
    #pragma unroll
    for (int t = 0; t < 4; t++) {
        int d = w + 16 * t;
        int path = d >> 5, k = d & 31;
        const float4* wr4 = (const float4*)((path ? w_hh_l1 : w_ih_l1) + k * CC);
        const float4* in4 = (const float4*)(path ? sin1 : sin0);
        float s = 0.f;
        #pragma unroll
        for (int j = lane; j < 128; j += 32) {
            float4 wv = wr4[j], iv = in4[j];
            s += iv.x * wv.x + iv.y * wv.y + iv.z * wv.z + iv.w * wv.w;
        }
        #pragma unroll
        for (int o = 16; o; o >>= 1) s += __shfl_down_sync(0xffffffffu, s, o);
        if (lane == 0) {
            float v = fmaxf(s + (path ? b_hh_l1 : b_ih_l1)[k], 0.f);
            if (path) hh[k] = v; else hi[k] = v;
        }
    }
    __syncthreads();

    // Phase 2: per-channel gate update (c = tid), float4 weight loads.
    int c = tid;
    float gi[3], gh[3];
    #pragma unroll
    for (int g = 0; g < 3; g++) { gi[g] = b_ih_l2[g * CC + c]; gh[g] = b_hh_l2[g * CC + c]; }
    #pragma unroll
    for (int g = 0; g < 3; g++) {
        const float4* wi4 = (const float4*)&w_ih_l2[(g * CC + c) * HID];
        const float4* wh4 = (const float4*)&w_hh_l2[(g * CC + c) * HID];
        #pragma unroll
        for (int q = 0; q < 8; q++) {
            float4 wi = wi4[q], wh = wh4[q];
            int k = q * 4;
            gi[g] += hi[k] * wi.x + hi[k+1] * wi.y + hi[k+2] * wi.z + hi[k+3] * wi.w;
            gh[g] += hh[k] * wh.x + hh[k+1] * wh.y + hh[k+2] * wh.z + hh[k+3] * wh.w;
        }
    }
    #pragma unroll
    for (int g = 0; g < 3; g++) g_gi[(b * 3 + g) * CC + c] = gi[g];
    float ig = sigmf(gi[0] + gh[0]);
    float fg = sigmf(gi[1] + gh[1]);
    float cg = tanhf(gi[2] + gh[2]);
    float nc = fg * g_ct[b * CC + c] + ig * cg;
    float nh = sigmf(nc);
    g_ct[b * CC + c] = nc;
    g_ht[b * CC + c] = nh;

    // Block-0 tail: second cell's hidden path with hx = ht[0] (our own fresh nh).
    if (b == 0) {
        sin0[c] = nh;
        __syncthreads();
        #pragma unroll
        for (int t = 0; t < 2; t++) {
            int k = w + 16 * t;
            const float4* wr4 = (const float4*)(w_hh_l1 + k * CC);
            const float4* in4 = (const float4*)sin0;
            float s = 0.f;
            #pragma unroll
            for (int j = lane; j < 128; j += 32) {
                float4 wv = wr4[j], iv = in4[j];
                s += iv.x * wv.x + iv.y * wv.y + iv.z * wv.z + iv.w * wv.w;
            }
            #pragma unroll
            for (int o = 16; o; o >>= 1) s += __shfl_down_sync(0xffffffffu, s, o);
            if (lane == 0) hi[k] = fmaxf(s + b_hh_l1[k], 0.f);
        }
        __syncthreads();
        #pragma unroll
        for (int j = tid; j < 3 * CC; j += 512) {
            float acc = b_hh_l2[j];
            const float4* wh4 = (const float4*)&w_hh_l2[j * HID];
            #pragma unroll
            for (int q = 0; q < 8; q++) {
                float4 wh = wh4[q];
                int k = q * 4;
                acc += hi[k] * wh.x + hi[k+1] * wh.y + hi[k+2] * wh.z + hi[k+3] * wh.w;
            }
            g_gh2[j] = acc;
        }
    }
}

// Per-plane scale = 1 + sigm(second-cell ncx). One thread per (b,c).
__global__ void __launch_bounds__(256) k_scale() {
    int idx = blockIdx.x * 256 + threadIdx.x;
    int b = idx >> 9, c = idx & 511;
    float i2 = g_gi[(b * 3 + 0) * CC + c] + g_gh2[c];
    float f2 = g_gi[(b * 3 + 1) * CC + c] + g_gh2[CC + c];
    float c2 = g_gi[(b * 3 + 2) * CC + c] + g_gh2[2 * CC + c];
    float nc2 = sigmf(f2) * g_ct[c] + sigmf(i2) * tanhf(c2);
    g_scale[idx] = 1.0f + sigmf(nc2);
}

// Fused update: x_new = x*scale + dwconv3x3(x); plane means for next layer.
// Two contiguous planes per block, 256 threads. PIXEL-STRIDED compute mapping
// (lane stride = 1 float in smem -> conflict-free LDS).
__global__ void __launch_bounds__(256) k_update(
        const float* __restrict__ xin, float* __restrict__ xout,
        const float* __restrict__ dw, int writeSeq) {
    int p0 = blockIdx.x * 2, tid = threadIdx.x;
    __shared__ __align__(16) float s[2 * HWSZ];
    __shared__ float sSc[2];

    const float4* in4 = (const float4*)(xin + (size_t)p0 * HWSZ);
    #pragma unroll
    for (int i = tid; i < 2 * QPP; i += 256) ((float4*)s)[i] = in4[i];
    if (tid < 2) sSc[tid] = g_scale[p0 + tid];
    __syncthreads();

    // load both channels' conv weights into registers
    int c0 = p0 & 511;
    float wq0[9], wq1[9];
    #pragma unroll
    for (int q = 0; q < 9; q++) { wq0[q] = dw[c0 * 9 + q]; wq1[q] = dw[(c0 + 1) * 9 + q]; }

    float* outp = xout + (size_t)p0 * HWSZ;
    float sum0 = 0.f, sum1 = 0.f;
    float sc0 = sSc[0], sc1 = sSc[1];

    #pragma unroll
    for (int i = tid; i < 2 * HWSZ; i += 256) {
        int pl = (i >= HWSZ);
        int p = i - pl * HWSZ;
        const float* sp = s + pl * HWSZ;
        const float* wq = pl ? wq1 : wq0;
        float scale = pl ? sc1 : sc0;
        int y = p / WW, x = p - y * WW;
        float conv;
        if (y > 0 && y < HH - 1 && x > 0 && x < WW - 1) {
            const float* r0 = sp + (y - 1) * WW + x;
            const float* r1 = r0 + WW;
            const float* r2 = r1 + WW;
            conv = wq[0] * r0[-1] + wq[1] * r0[0] + wq[2] * r0[1]
                 + wq[3] * r1[-1] + wq[4] * r1[0] + wq[5] * r1[1]
                 + wq[6] * r2[-1] + wq[7] * r2[0] + wq[8] * r2[1];
        } else {
            conv = 0.f;
            #pragma unroll
            for (int dy = -1; dy <= 1; dy++) {
                int yy = y + dy;
                if (yy < 0 || yy >= HH) continue;
                #pragma unroll
                for (int dx = -1; dx <= 1; dx++) {
                    int xx = x + dx;
                    if (xx < 0 || xx >= WW) continue;
                    conv += wq[(dy + 1) * 3 + (dx + 1)] * sp[yy * WW + xx];
                }
            }
        }
        float o = sp[p] * scale + conv;
        outp[i] = o;
        if (pl) sum1 += o; else sum0 += o;
    }
    if (writeSeq) {
        __syncthreads();
        blockReduceSum2(sum0, sum1);
        if (tid == 0) {
            g_seq[p0] = sum0 * (1.0f / HWSZ);
            g_seq[p0 + 1] = sum1 * (1.0f / HWSZ);
        }
    }
}

extern "C" void kernel_launch(void* const* d_in, const int* in_sizes, int n_in,
                              void* d_out, int out_size) {
    const float* x        = (const float*)d_in[0];
    const float* w_ih_l1  = (const float*)d_in[1];
    const float* b_ih_l1  = (const float*)d_in[2];
    const float* w_ih_l2  = (const float*)d_in[3];
    const float* b_ih_l2  = (const float*)d_in[4];
    const float* w_hh_l1  = (const float*)d_in[5];
    const float* b_hh_l1  = (const float*)d_in[6];
    const float* w_hh_l2  = (const float*)d_in[7];
    const float* b_hh_l2  = (const float*)d_in[8];
    const float* dw       = (const float*)d_in[9];
    float* out = (float*)d_out;

    float* buf = nullptr;
    cudaGetSymbolAddress((void**)&buf, g_buf);

    k_pool_init<<<NPLANE / 2, 256>>>(x);

    const float* cur = x;
    for (int l = 0; l < NLAYERS; l++) {
        k_cell<<<BB, 512>>>(w_ih_l1, b_ih_l1, w_ih_l2, b_ih_l2,
                            w_hh_l1, b_hh_l1, w_hh_l2, b_hh_l2);
        k_scale<<<NPLANE / 256, 256>>>();
        float* nxt = ((l & 1) == 0) ? buf : out;   // l0->buf, l1->out, l2->buf, l3->out
        k_update<<<NPLANE / 2, 256>>>(cur, nxt, dw, (l < NLAYERS - 1) ? 1 : 0);
        cur = nxt;
    }
}

// round 6
// speedup vs baseline: 2.4038x; 1.8547x over previous
#include <cuda_runtime.h>

#define BB 64
#define CC 512
#define HH 28
#define WW 28
#define HWSZ (HH*WW)
#define HID 32
#define NPLANE (BB*CC)
#define NLAYERS 4
#define QPP 196            // float4 quads per plane
#define PPB 8              // planes per block (1 warp each)

// Scratch (static device memory -- allocation-free)
__device__ float g_buf[(size_t)NPLANE * HWSZ];   // ping-pong x buffer (~103MB)
__device__ float g_seq[NPLANE];                  // pooled means [B,C]
__device__ float g_ht[NPLANE];                   // LSTM hidden
__device__ float g_ct[NPLANE];                   // LSTM cell
__device__ float g_gi[BB * 3 * CC];              // input-path gates (reused by 2nd cell)
__device__ float g_gh2[3 * CC];                  // 2nd cell hidden-path gates (row 0)

__device__ __forceinline__ float sigmf(float x) { return 1.0f / (1.0f + __expf(-x)); }

// Initial pool of x + zero LSTM state. Warp-per-plane, no block sync.
__global__ void __launch_bounds__(256) k_pool_init(const float* __restrict__ x) {
    int lane = threadIdx.x & 31, w = threadIdx.x >> 5;
    int plane = blockIdx.x * PPB + w;
    const float4* in4 = (const float4*)(x + (size_t)plane * HWSZ);
    float s = 0.f;
    #pragma unroll
    for (int q = lane; q < QPP; q += 32) {
        float4 v = in4[q];
        s += v.x + v.y + v.z + v.w;
    }
    #pragma unroll
    for (int o = 16; o; o >>= 1) s += __shfl_down_sync(0xffffffffu, s, o);
    if (lane == 0) {
        g_seq[plane] = s * (1.0f / HWSZ);
        g_ht[plane] = 0.f;
        g_ct[plane] = 0.f;
    }
}

// Fused cell: bottleneck GEMVs (both paths) + gate update for one batch b per block.
// Block 0 additionally computes the second cell's hidden path (ht[0] -> g_gh2).
__global__ void __launch_bounds__(512) k_cell(
        const float* __restrict__ w_ih_l1, const float* __restrict__ b_ih_l1,
        const float* __restrict__ w_ih_l2, const float* __restrict__ b_ih_l2,
        const float* __restrict__ w_hh_l1, const float* __restrict__ b_hh_l1,
        const float* __restrict__ w_hh_l2, const float* __restrict__ b_hh_l2) {
    __shared__ __align__(16) float sin0[CC], sin1[CC];
    __shared__ float hi[HID], hh[HID];
    int b = blockIdx.x, tid = threadIdx.x, lane = tid & 31, w = tid >> 5;  // 16 warps

    if (tid < 128)      ((float4*)sin0)[tid]       = ((const float4*)(g_seq + b * CC))[tid];
    else if (tid < 256) ((float4*)sin1)[tid - 128] = ((const float4*)(g_ht + b * CC))[tid - 128];
    __syncthreads();

    // Phase 1: 64 dots of length 512 (2 paths x 32 hidden), float4 loads.
    #pragma unroll
    for (int t = 0; t < 4; t++) {
        int d = w + 16 * t;
        int path = d >> 5, k = d & 31;
        const float4* wr4 = (const float4*)((path ? w_hh_l1 : w_ih_l1) + k * CC);
        const float4* in4 = (const float4*)(path ? sin1 : sin0);
        float s = 0.f;
        #pragma unroll
        for (int j = lane; j < 128; j += 32) {
            float4 wv = wr4[j], iv = in4[j];
            s += iv.x * wv.x + iv.y * wv.y + iv.z * wv.z + iv.w * wv.w;
        }
        #pragma unroll
        for (int o = 16; o; o >>= 1) s += __shfl_down_sync(0xffffffffu, s, o);
        if (lane == 0) {
            float v = fmaxf(s + (path ? b_hh_l1 : b_ih_l1)[k], 0.f);
            if (path) hh[k] = v; else hi[k] = v;
        }
    }
    __syncthreads();

    // Phase 2: per-channel gate update (c = tid), float4 weight loads.
    int c = tid;
    float gi[3], gh[3];
    #pragma unroll
    for (int g = 0; g < 3; g++) { gi[g] = b_ih_l2[g * CC + c]; gh[g] = b_hh_l2[g * CC + c]; }
    #pragma unroll
    for (int g = 0; g < 3; g++) {
        const float4* wi4 = (const float4*)&w_ih_l2[(g * CC + c) * HID];
        const float4* wh4 = (const float4*)&w_hh_l2[(g * CC + c) * HID];
        #pragma unroll
        for (int q = 0; q < 8; q++) {
            float4 wi = wi4[q], wh = wh4[q];
            int k = q * 4;
            gi[g] += hi[k] * wi.x + hi[k+1] * wi.y + hi[k+2] * wi.z + hi[k+3] * wi.w;
            gh[g] += hh[k] * wh.x + hh[k+1] * wh.y + hh[k+2] * wh.z + hh[k+3] * wh.w;
        }
    }
    #pragma unroll
    for (int g = 0; g < 3; g++) g_gi[(b * 3 + g) * CC + c] = gi[g];
    float ig = sigmf(gi[0] + gh[0]);
    float fg = sigmf(gi[1] + gh[1]);
    float cg = tanhf(gi[2] + gh[2]);
    float nc = fg * g_ct[b * CC + c] + ig * cg;
    float nh = sigmf(nc);
    g_ct[b * CC + c] = nc;
    g_ht[b * CC + c] = nh;

    // Block-0 tail: second cell's hidden path with hx = ht[0] (our own fresh nh).
    if (b == 0) {
        sin0[c] = nh;
        __syncthreads();
        #pragma unroll
        for (int t = 0; t < 2; t++) {
            int k = w + 16 * t;
            const float4* wr4 = (const float4*)(w_hh_l1 + k * CC);
            const float4* in4 = (const float4*)sin0;
            float s = 0.f;
            #pragma unroll
            for (int j = lane; j < 128; j += 32) {
                float4 wv = wr4[j], iv = in4[j];
                s += iv.x * wv.x + iv.y * wv.y + iv.z * wv.z + iv.w * wv.w;
            }
            #pragma unroll
            for (int o = 16; o; o >>= 1) s += __shfl_down_sync(0xffffffffu, s, o);
            if (lane == 0) hi[k] = fmaxf(s + b_hh_l1[k], 0.f);
        }
        __syncthreads();
        #pragma unroll
        for (int j = tid; j < 3 * CC; j += 512) {
            float acc = b_hh_l2[j];
            const float4* wh4 = (const float4*)&w_hh_l2[j * HID];
            #pragma unroll
            for (int q = 0; q < 8; q++) {
                float4 wh = wh4[q];
                int k = q * 4;
                acc += hi[k] * wh.x + hi[k+1] * wh.y + hi[k+2] * wh.z + hi[k+3] * wh.w;
            }
            g_gh2[j] = acc;
        }
    }
}

// Fused update: x_new = x*scale + dwconv3x3(x); plane means for next layer.
// Warp-per-plane register-rolling stencil: lane = column, 1 LDS + 2 SHFL per
// row per lane, scale gates computed inline, plane mean via warp reduce.
__global__ void __launch_bounds__(256) k_update(
        const float* __restrict__ xin, float* __restrict__ xout,
        const float* __restrict__ dw, int writeSeq) {
    __shared__ __align__(16) float s[PPB * HWSZ + 4];
    int lane = threadIdx.x & 31, w = threadIdx.x >> 5;
    int plane = blockIdx.x * PPB + w;
    int b = plane >> 9, c = plane & 511;
    float* sp = s + w * HWSZ;

    // stage plane via float4 (7 wide loads per lane, high MLP)
    const float4* in4 = (const float4*)(xin + (size_t)plane * HWSZ);
    float4* sp4 = (float4*)sp;
    #pragma unroll
    for (int q = lane; q < QPP; q += 32) sp4[q] = in4[q];

    // second-cell scale, lane-parallel gate loads
    float tg = 0.f;
    if (lane < 3) tg = g_gi[(b * 3 + lane) * CC + c] + g_gh2[lane * CC + c];
    else if (lane == 3) tg = g_ct[c];
    float i2  = __shfl_sync(0xffffffffu, tg, 0);
    float f2  = __shfl_sync(0xffffffffu, tg, 1);
    float c2  = __shfl_sync(0xffffffffu, tg, 2);
    float ct0 = __shfl_sync(0xffffffffu, tg, 3);
    float scale = 1.0f + sigmf(sigmf(f2) * ct0 + sigmf(i2) * tanhf(c2));

    float wq[9];
    const float* wp = dw + c * 9;
    #pragma unroll
    for (int q = 0; q < 9; q++) wq[q] = wp[q];   // converged broadcast loads

    __syncwarp();

    int x = lane;
    bool active = x < WW;
    int xi = active ? x : 0;
    bool notL = (x > 0), notR = (x < WW - 1);

    float aL = 0, aC = 0, aR = 0, bL, bC, bR, cL, cC, cR;
    bC = sp[xi];
    bL = __shfl_up_sync(0xffffffffu, bC, 1);   if (!notL) bL = 0;
    bR = __shfl_down_sync(0xffffffffu, bC, 1); if (!notR) bR = 0;
    cC = sp[WW + xi];
    cL = __shfl_up_sync(0xffffffffu, cC, 1);   if (!notL) cL = 0;
    cR = __shfl_down_sync(0xffffffffu, cC, 1); if (!notR) cR = 0;

    float* outp = xout + (size_t)plane * HWSZ;
    float sum = 0.f;
    #pragma unroll
    for (int y = 0; y < HH; y++) {
        float conv = wq[0] * aL + wq[1] * aC + wq[2] * aR
                   + wq[3] * bL + wq[4] * bC + wq[5] * bR
                   + wq[6] * cL + wq[7] * cC + wq[8] * cR;
        float o = fmaf(bC, scale, conv);
        if (active) { outp[y * WW + x] = o; sum += o; }
        aL = bL; aC = bC; aR = bR;
        bL = cL; bC = cC; bR = cR;
        if (y + 2 < HH) {
            cC = sp[(y + 2) * WW + xi];
            cL = __shfl_up_sync(0xffffffffu, cC, 1);   if (!notL) cL = 0;
            cR = __shfl_down_sync(0xffffffffu, cC, 1); if (!notR) cR = 0;
        } else { cC = cL = cR = 0.f; }
    }
    if (writeSeq) {
        #pragma unroll
        for (int o2 = 16; o2; o2 >>= 1) sum += __shfl_down_sync(0xffffffffu, sum, o2);
        if (lane == 0) g_seq[plane] = sum * (1.0f / HWSZ);
    }
}

extern "C" void kernel_launch(void* const* d_in, const int* in_sizes, int n_in,
                              void* d_out, int out_size) {
    const float* x        = (const float*)d_in[0];
    const float* w_ih_l1  = (const float*)d_in[1];
    const float* b_ih_l1  = (const float*)d_in[2];
    const float* w_ih_l2  = (const float*)d_in[3];
    const float* b_ih_l2  = (const float*)d_in[4];
    const float* w_hh_l1  = (const float*)d_in[5];
    const float* b_hh_l1  = (const float*)d_in[6];
    const float* w_hh_l2  = (const float*)d_in[7];
    const float* b_hh_l2  = (const float*)d_in[8];
    const float* dw       = (const float*)d_in[9];
    float* out = (float*)d_out;

    float* buf = nullptr;
    cudaGetSymbolAddress((void**)&buf, g_buf);

    k_pool_init<<<NPLANE / PPB, 256>>>(x);

    const float* cur = x;
    for (int l = 0; l < NLAYERS; l++) {
        k_cell<<<BB, 512>>>(w_ih_l1, b_ih_l1, w_ih_l2, b_ih_l2,
                            w_hh_l1, b_hh_l1, w_hh_l2, b_hh_l2);
        float* nxt = ((l & 1) == 0) ? buf : out;   // l0->buf, l1->out, l2->buf, l3->out
        k_update<<<NPLANE / PPB, 256>>>(cur, nxt, dw, (l < NLAYERS - 1) ? 1 : 0);
        cur = nxt;
    }
}